// round 5
// baseline (speedup 1.0000x reference)
#include <cuda_runtime.h>
#include <cuda_fp16.h>
#include <mma.h>
#include <cstdint>

using namespace nvcuda;

// Problem dims (fixed by setup_inputs)
constexpr int U = 128, I = 256, J = 512, C = 128, E = 128;

// ---------------- scratch (device globals; no allocation allowed) ----------
__device__ float  g_skb[U * J];            // inter . w2 + b
__device__ float  g_upart[U * C];          // user @ W1 + b_mlp
__device__ float  g_maskf[U * J];          // canonical mask as float 0/1
__device__ int    g_mask_mode;             // 0=byte, 1=int32, 2=float32
__device__ __half g_W2h[C * C];            // W_mlp[E:], fp16
__device__ __half g_Zh[U * J * C];         // Z = interacted @ W2, fp16

// ---------------- mask dtype sniffing (reads first 16384 words only) -------
__global__ void detect_mask_kernel(const unsigned* __restrict__ m)
{
    __shared__ int s_a, s_b;
    if (threadIdx.x == 0) { s_a = 0; s_b = 0; }
    __syncthreads();
    int a = 0, b = 0;
    for (int i = threadIdx.x; i < (U * J) / 4; i += blockDim.x) {
        unsigned w = m[i];
        a |= (w != 0u && w != 1u);
        b |= (w != 0u && w != 0x3F800000u);
    }
    if (a) atomicOr(&s_a, 1);
    if (b) atomicOr(&s_b, 1);
    __syncthreads();
    if (threadIdx.x == 0) {
        int mode;
        if (!s_a)      mode = 1;   // int32 0/1
        else if (!s_b) mode = 2;   // float32 0/1.0
        else           mode = 0;   // packed bool bytes
        g_mask_mode = mode;
    }
}

__global__ __launch_bounds__(256) void maskconv_kernel(const void* __restrict__ m)
{
    int i = blockIdx.x * 256 + threadIdx.x;
    int mode = g_mask_mode;
    int v;
    if (mode == 1)      v = ((const int*)m)[i] != 0;
    else if (mode == 2) v = ((const float*)m)[i] != 0.f;
    else                v = ((const unsigned char*)m)[i] != 0;
    g_maskf[i] = (float)v;
}

// ---------------- u_part = user @ W_mlp[:E] + b_mlp -------------------------
__global__ void upart_kernel(const float* __restrict__ user,
                             const float* __restrict__ Wmlp,
                             const float* __restrict__ bmlp)
{
    int u = blockIdx.x, c = threadIdx.x;
    float acc = bmlp[c];
    #pragma unroll 8
    for (int e = 0; e < E; e++)
        acc += user[u * E + e] * __ldg(Wmlp + e * C + c);
    g_upart[u * C + c] = acc;
}

// ---------------- W2 -> fp16 -------------------------------------------------
__global__ void w2conv_kernel(const float* __restrict__ Wmlp)
{
    int i = blockIdx.x * blockDim.x + threadIdx.x;
    if (i < C * C) g_W2h[i] = __float2half(Wmlp[E * C + i]);
}

// ---------------- shared MMA micro-tile (BM=64, BN=128, BK=64, 8 warps) ----
template<int LDA, int LDB>
__device__ __forceinline__ void mma_tile(
    const __half* A, const __half* B, int wm, int wn,
    wmma::fragment<wmma::accumulator, 16, 16, 16, float> (&acc)[2][2])
{
    #pragma unroll
    for (int kk = 0; kk < 64; kk += 16) {
        wmma::fragment<wmma::matrix_a, 16, 16, 16, __half, wmma::row_major> a[2];
        wmma::fragment<wmma::matrix_b, 16, 16, 16, __half, wmma::row_major> b[2];
        wmma::load_matrix_sync(a[0], A + (wm * 32) * LDA + kk, LDA);
        wmma::load_matrix_sync(a[1], A + (wm * 32 + 16) * LDA + kk, LDA);
        wmma::load_matrix_sync(b[0], B + kk * LDB + wn * 32, LDB);
        wmma::load_matrix_sync(b[1], B + kk * LDB + wn * 32 + 16, LDB);
        #pragma unroll
        for (int fi = 0; fi < 2; fi++)
            #pragma unroll
            for (int fj = 0; fj < 2; fj++)
                wmma::mma_sync(acc[fi][fj], a[fi], b[fj], acc[fi][fj]);
    }
}

// ---------------- fusedZ: one read of inter -> skb + Zh fp16 ---------------
// grid (J/64, U), 256 thr. Per block: 64 j-rows of one user.
__global__ __launch_bounds__(256) void fusedz_kernel(
    const float* __restrict__ inter, const float* __restrict__ w2,
    const float* __restrict__ bd)
{
    __shared__ __align__(16) char sm[64 * 136 * 2 * 2];  // As + Bs (34,816 B)
    __half* As = (__half*)sm;                 // 64 x 128 (lda 136)
    __half* Bs = (__half*)(sm + 64 * 136 * 2);
    float*  Cs = (float*)sm;                  // epilogue staging (32 KB)

    const int u = blockIdx.y, j0 = blockIdx.x * 64;
    const int tid = threadIdx.x, wid = tid >> 5, lane = tid & 31;
    const int wm = wid >> 2, wn = wid & 3;

    const float4 wv = __ldg((const float4*)w2 + lane);
    const float bias = __ldg(bd);

    // load + convert + skb dot (warp per row, 8 rows per warp)
    #pragma unroll
    for (int r = 0; r < 8; r++) {
        int row = wid + 8 * r;
        float4 v = *(const float4*)(inter + ((size_t)(u * J + j0 + row)) * C + lane * 4);
        __half2 h01 = __floats2half2_rn(v.x, v.y);
        __half2 h23 = __floats2half2_rn(v.z, v.w);
        uint2 pk;
        pk.x = *(unsigned*)&h01; pk.y = *(unsigned*)&h23;
        *(uint2*)(As + row * 136 + lane * 4) = pk;
        float d = v.x * wv.x + v.y * wv.y + v.z * wv.z + v.w * wv.w;
        #pragma unroll
        for (int off = 16; off; off >>= 1) d += __shfl_xor_sync(0xffffffffu, d, off);
        if (lane == 0) g_skb[u * J + j0 + row] = d + bias;
    }
    __syncthreads();

    wmma::fragment<wmma::accumulator, 16, 16, 16, float> acc[2][2];
    #pragma unroll
    for (int fi = 0; fi < 2; fi++)
        for (int fj = 0; fj < 2; fj++) wmma::fill_fragment(acc[fi][fj], 0.f);

    for (int k0 = 0; k0 < C; k0 += 64) {
        #pragma unroll
        for (int r = 0; r < 4; r++) {
            int idx = tid + 256 * r, br = idx >> 4, bc = (idx & 15) * 8;
            *(int4*)(Bs + br * 136 + bc) = *(const int4*)(g_W2h + (k0 + br) * C + bc);
        }
        __syncthreads();
        mma_tile<136, 136>(As + k0, Bs, wm, wn, acc);
        __syncthreads();
    }

    // epilogue: acc -> Cs (union over As/Bs) -> fp16 Zh
    #pragma unroll
    for (int fi = 0; fi < 2; fi++)
        for (int fj = 0; fj < 2; fj++)
            wmma::store_matrix_sync(
                Cs + (wm * 32 + fi * 16) * 128 + wn * 32 + fj * 16,
                acc[fi][fj], 128, wmma::mem_row_major);
    __syncthreads();
    #pragma unroll
    for (int it = 0; it < 8; it++) {
        int idx = tid + 256 * it, row = idx >> 5, c4 = (idx & 31) * 4;
        float4 v = *(const float4*)(Cs + row * 128 + c4);
        __half2 h01 = __floats2half2_rn(v.x, v.y);
        __half2 h23 = __floats2half2_rn(v.z, v.w);
        uint2 pk; pk.x = *(unsigned*)&h01; pk.y = *(unsigned*)&h23;
        *(uint2*)(g_Zh + ((size_t)(u * J + j0 + row)) * C + c4) = pk;
    }
}

// ---------------- gemm_main: fused attention + pooling + MLP ----------------
// grid (I/64, U), 256 thr, 104 KB dynamic smem, 1 CTA/SM.
// Phase 0: st[64] from target (warp dots); load skb/mask.
// Phase 1: w = exp(tanh(st+skb))*mask -> smem fp16 (64x512); rowsum -> inv.
// Phase 1d: attn output = w*inv (fp32, coalesced).
// Phase 2: (w @ Zh) k-loop MMA; epilogue relu(acc*inv + upart) -> out.
constexpr int LDW  = 520;                         // wsm half stride (padded)
constexpr int UOFF = 64 * LDW * 2;                // 66,560: union (Bs / Cs)
constexpr int SOFF = UOFF + 64 * 128 * 4;         // 99,328: small arrays
constexpr int SMEM_MAIN = SOFF + (64 + 64 + 512 + 512) * 4;  // 103,936

__global__ __launch_bounds__(256, 1) void gemm_main_kernel(
    const float* __restrict__ target, const float* __restrict__ w1,
    float* __restrict__ out_ctx, float* __restrict__ out_attn)
{
    extern __shared__ __align__(16) char dsm[];
    __half* wsm   = (__half*)dsm;
    __half* Bs    = (__half*)(dsm + UOFF);
    float*  Cs    = (float*)(dsm + UOFF);
    float* st_sm  = (float*)(dsm + SOFF);
    float* inv_sm = st_sm + 64;
    float* skb_sm = inv_sm + 64;
    float* m_sm   = skb_sm + 512;

    const int u = blockIdx.y, m0 = blockIdx.x * 64;
    const int tid = threadIdx.x, wid = tid >> 5, lane = tid & 31;
    const int wm = wid >> 2, wn = wid & 3;
    const float L2E = 1.4426950408889634f;

    // load skb + mask for this user
    for (int k = tid; k < 512; k += 256) {
        skb_sm[k] = g_skb[u * J + k];
        m_sm[k]   = g_maskf[u * J + k];
    }
    // st from target (warp per row)
    {
        float4 wv = __ldg((const float4*)w1 + lane);
        #pragma unroll
        for (int r = 0; r < 8; r++) {
            int row = wid + 8 * r;
            float4 v = *(const float4*)(target + ((size_t)(u * I + m0 + row)) * C + lane * 4);
            float d = v.x * wv.x + v.y * wv.y + v.z * wv.z + v.w * wv.w;
            #pragma unroll
            for (int off = 16; off; off >>= 1) d += __shfl_xor_sync(0xffffffffu, d, off);
            if (lane == 0) st_sm[row] = d;
        }
    }
    __syncthreads();

    // phase 1: w tiles + row sums (4 threads per row, 128 cols each)
    {
        int row = tid >> 2, cb = (tid & 3) * 128;
        float stv = st_sm[row];
        float sum = 0.f;
        #pragma unroll 8
        for (int c = 0; c < 128; c += 2) {
            float x0 = stv + skb_sm[cb + c], x1 = stv + skb_sm[cb + c + 1];
            float t0, t1, e0, e1;
            asm("tanh.approx.f32 %0,%1;" : "=f"(t0) : "f"(x0));
            asm("tanh.approx.f32 %0,%1;" : "=f"(t1) : "f"(x1));
            asm("ex2.approx.f32 %0,%1;"  : "=f"(e0) : "f"(t0 * L2E));
            asm("ex2.approx.f32 %0,%1;"  : "=f"(e1) : "f"(t1 * L2E));
            e0 *= m_sm[cb + c]; e1 *= m_sm[cb + c + 1];
            *(__half2*)(wsm + row * LDW + cb + c) = __floats2half2_rn(e0, e1);
            sum += e0 + e1;
        }
        sum += __shfl_xor_sync(0xffffffffu, sum, 1);
        sum += __shfl_xor_sync(0xffffffffu, sum, 2);
        if ((tid & 3) == 0) inv_sm[row] = __fdividef(1.f, sum);
    }
    __syncthreads();

    // phase 1d: attn output (coalesced float4 stores)
    {
        float* ab = out_attn + ((size_t)(u * I + m0)) * J;
        #pragma unroll
        for (int it = 0; it < 32; it++) {
            int idx = tid + 256 * it;
            int row = idx >> 7, c4 = (idx & 127) * 4;
            uint2 pk = *(uint2*)(wsm + row * LDW + c4);
            __half2 h01 = *(__half2*)&pk.x, h23 = *(__half2*)&pk.y;
            float iv = inv_sm[row];
            float2 f01 = __half22float2(h01), f23 = __half22float2(h23);
            float4 o = make_float4(f01.x * iv, f01.y * iv, f23.x * iv, f23.y * iv);
            *(float4*)(ab + row * J + c4) = o;
        }
    }

    // phase 2: MMA over J in 8 k-tiles of 64
    wmma::fragment<wmma::accumulator, 16, 16, 16, float> acc[2][2];
    #pragma unroll
    for (int fi = 0; fi < 2; fi++)
        for (int fj = 0; fj < 2; fj++) wmma::fill_fragment(acc[fi][fj], 0.f);

    for (int k0 = 0; k0 < J; k0 += 64) {
        #pragma unroll
        for (int r = 0; r < 4; r++) {
            int idx = tid + 256 * r, br = idx >> 4, bc = (idx & 15) * 8;
            *(int4*)(Bs + br * 136 + bc) =
                *(const int4*)(g_Zh + ((size_t)u * J + k0 + br) * C + bc);
        }
        __syncthreads();
        mma_tile<LDW, 136>(wsm + k0, Bs, wm, wn, acc);
        __syncthreads();
    }

    // epilogue: acc*inv + upart, relu
    #pragma unroll
    for (int fi = 0; fi < 2; fi++)
        for (int fj = 0; fj < 2; fj++)
            wmma::store_matrix_sync(
                Cs + (wm * 32 + fi * 16) * 128 + wn * 32 + fj * 16,
                acc[fi][fj], 128, wmma::mem_row_major);
    __syncthreads();

    const float4* up4 = (const float4*)(g_upart + u * C);
    float* ob = out_ctx + ((size_t)(u * I + m0)) * C;
    #pragma unroll
    for (int it = 0; it < 8; it++) {
        int idx = tid + 256 * it, row = idx >> 5, c4 = idx & 31;
        float4 v = ((const float4*)Cs)[idx];
        float iv = inv_sm[row];
        float4 up = __ldg(up4 + c4);
        v.x = fmaxf(fmaf(v.x, iv, up.x), 0.f);
        v.y = fmaxf(fmaf(v.y, iv, up.y), 0.f);
        v.z = fmaxf(fmaf(v.z, iv, up.z), 0.f);
        v.w = fmaxf(fmaf(v.w, iv, up.w), 0.f);
        ((float4*)ob)[idx] = v;
    }
}

// ---------------- launcher ---------------------------------------------------
extern "C" void kernel_launch(void* const* d_in, const int* in_sizes, int n_in,
                              void* d_out, int out_size)
{
    const float* target = (const float*)d_in[0];  // (U,I,C)
    const float* inter  = (const float*)d_in[1];  // (U,J,C)
    const float* user   = (const float*)d_in[2];  // (U,E)
    const void*  mask   = d_in[3];                // (U,J) dtype sniffed
    const float* wdense = (const float*)d_in[4];  // (2C,)
    const float* bdense = (const float*)d_in[5];  // (1,)
    const float* Wmlp   = (const float*)d_in[6];  // (E+C, C)
    const float* bmlp   = (const float*)d_in[7];  // (C,)

    float* out_ctx  = (float*)d_out;                       // (U,I,C)
    float* out_attn = (float*)d_out + (size_t)U * I * C;   // (U,I,J)

    cudaFuncSetAttribute(gemm_main_kernel,
                         cudaFuncAttributeMaxDynamicSharedMemorySize, SMEM_MAIN);

    detect_mask_kernel<<<1, 1024>>>((const unsigned*)mask);
    maskconv_kernel<<<(U * J) / 256, 256>>>(mask);
    w2conv_kernel<<<(C * C) / 256, 256>>>(Wmlp);
    upart_kernel<<<U, C>>>(user, Wmlp, bmlp);

    fusedz_kernel<<<dim3(J / 64, U), 256>>>(inter, wdense + C, bdense);
    gemm_main_kernel<<<dim3(I / 64, U), 256, SMEM_MAIN>>>(target, wdense,
                                                          out_ctx, out_attn);
}

// round 6
// speedup vs baseline: 1.3120x; 1.3120x over previous
#include <cuda_runtime.h>
#include <cuda_fp16.h>
#include <mma.h>
#include <cstdint>

using namespace nvcuda;

// Problem dims (fixed by setup_inputs)
constexpr int U = 128, I = 256, J = 512, C = 128, E = 128;

// ---------------- scratch (device globals) ----------------------------------
__device__ float  g_skb[U * J];            // inter . w2 + b
__device__ float  g_upart[U * C];          // user @ W1 + b_mlp
__device__ int    g_mask_mode;             // 0=byte, 1=int32, 2=float32
__device__ __half g_Zh[U * J * C];         // Z = interacted @ W2, fp16

// ---------------- cp.async helpers ------------------------------------------
__device__ __forceinline__ void cp_async16(void* smem, const void* gmem)
{
    unsigned s = (unsigned)__cvta_generic_to_shared(smem);
    asm volatile("cp.async.cg.shared.global [%0], [%1], 16;" :: "r"(s), "l"(gmem));
}
__device__ __forceinline__ void cp_commit()
{
    asm volatile("cp.async.commit_group;" ::: "memory");
}
template<int N>
__device__ __forceinline__ void cp_wait()
{
    asm volatile("cp.async.wait_group %0;" :: "n"(N) : "memory");
}

// ---------------- mask dtype sniffing (reads first 16384 words only) -------
__global__ void detect_mask_kernel(const unsigned* __restrict__ m)
{
    __shared__ int s_a, s_b;
    if (threadIdx.x == 0) { s_a = 0; s_b = 0; }
    __syncthreads();
    int a = 0, b = 0;
    for (int i = threadIdx.x; i < (U * J) / 4; i += blockDim.x) {
        unsigned w = m[i];
        a |= (w != 0u && w != 1u);
        b |= (w != 0u && w != 0x3F800000u);
    }
    if (a) atomicOr(&s_a, 1);
    if (b) atomicOr(&s_b, 1);
    __syncthreads();
    if (threadIdx.x == 0) {
        int mode;
        if (!s_a)      mode = 1;   // int32 0/1
        else if (!s_b) mode = 2;   // float32 0/1.0
        else           mode = 0;   // packed bool bytes
        g_mask_mode = mode;
    }
}

// ---------------- shared MMA micro-tile (BM=64, BN=128, BK=64, 8 warps) ----
template<int LDA, int LDB>
__device__ __forceinline__ void mma_tile(
    const __half* A, const __half* B, int wm, int wn,
    wmma::fragment<wmma::accumulator, 16, 16, 16, float> (&acc)[2][2])
{
    #pragma unroll
    for (int kk = 0; kk < 64; kk += 16) {
        wmma::fragment<wmma::matrix_a, 16, 16, 16, __half, wmma::row_major> a[2];
        wmma::fragment<wmma::matrix_b, 16, 16, 16, __half, wmma::row_major> b[2];
        wmma::load_matrix_sync(a[0], A + (wm * 32) * LDA + kk, LDA);
        wmma::load_matrix_sync(a[1], A + (wm * 32 + 16) * LDA + kk, LDA);
        wmma::load_matrix_sync(b[0], B + kk * LDB + wn * 32, LDB);
        wmma::load_matrix_sync(b[1], B + kk * LDB + wn * 32 + 16, LDB);
        #pragma unroll
        for (int fi = 0; fi < 2; fi++)
            #pragma unroll
            for (int fj = 0; fj < 2; fj++)
                wmma::mma_sync(acc[fi][fj], a[fi], b[fj], acc[fi][fj]);
    }
}

// ---------------- fusedZ: inter -> skb + Zh fp16; upart rides along --------
// grid (9, U), 256 thr. blockIdx.x<8: 64 j-rows of user u. ==8: upart for u.
__global__ __launch_bounds__(256) void fusedz_kernel(
    const float* __restrict__ inter, const float* __restrict__ w2,
    const float* __restrict__ bd, const float* __restrict__ user,
    const float* __restrict__ Wmlp, const float* __restrict__ bmlp)
{
    __shared__ __align__(16) char sm[64 * 136 * 2 * 2];  // 34,816 B
    const int u = blockIdx.y;
    const int tid = threadIdx.x, wid = tid >> 5, lane = tid & 31;

    if (blockIdx.x == 8) {
        // ---- upart: g_upart[u] = user[u] @ Wmlp[:E] + bmlp ----
        float* usm  = (float*)sm;          // 128 floats
        float* psum = usm + 128;           // 256 floats
        if (tid < 128) usm[tid] = user[u * E + tid];
        __syncthreads();
        int c = tid & 127, h = tid >> 7;
        float acc0 = 0.f, acc1 = 0.f;
        int e0 = h * 64;
        #pragma unroll 16
        for (int e = 0; e < 64; e += 2) {
            acc0 += usm[e0 + e]     * __ldg(Wmlp + (e0 + e) * C + c);
            acc1 += usm[e0 + e + 1] * __ldg(Wmlp + (e0 + e + 1) * C + c);
        }
        psum[tid] = acc0 + acc1;
        __syncthreads();
        if (tid < 128)
            g_upart[u * C + tid] = psum[tid] + psum[tid + 128] + __ldg(bmlp + tid);
        return;
    }

    // ---- fusedz main path ----
    __half* As = (__half*)sm;                    // 64 x 128 (lda 136)
    __half* Bs = (__half*)(sm + 64 * 136 * 2);
    float*  Cs = (float*)sm;                     // epilogue staging (32 KB)
    const int j0 = blockIdx.x * 64;
    const int wm = wid >> 2, wn = wid & 3;

    const float4 wv = __ldg((const float4*)w2 + lane);
    const float bias = __ldg(bd);

    // load + convert + skb dot (warp per row, 8 rows per warp)
    #pragma unroll
    for (int r = 0; r < 8; r++) {
        int row = wid + 8 * r;
        float4 v = *(const float4*)(inter + ((size_t)(u * J + j0 + row)) * C + lane * 4);
        __half2 h01 = __floats2half2_rn(v.x, v.y);
        __half2 h23 = __floats2half2_rn(v.z, v.w);
        uint2 pk;
        pk.x = *(unsigned*)&h01; pk.y = *(unsigned*)&h23;
        *(uint2*)(As + row * 136 + lane * 4) = pk;
        float d = v.x * wv.x + v.y * wv.y + v.z * wv.z + v.w * wv.w;
        #pragma unroll
        for (int off = 16; off; off >>= 1) d += __shfl_xor_sync(0xffffffffu, d, off);
        if (lane == 0) g_skb[u * J + j0 + row] = d + bias;
    }
    __syncthreads();

    wmma::fragment<wmma::accumulator, 16, 16, 16, float> acc[2][2];
    #pragma unroll
    for (int fi = 0; fi < 2; fi++)
        for (int fj = 0; fj < 2; fj++) wmma::fill_fragment(acc[fi][fj], 0.f);

    for (int k0 = 0; k0 < C; k0 += 64) {
        // Bs <- W_mlp[E+k0 .. E+k0+63, :] converted fp32->fp16 (L2-hot)
        #pragma unroll
        for (int r = 0; r < 8; r++) {
            int idx = tid + 256 * r;            // 2048 float4 slots
            int br = idx >> 5, bc = (idx & 31) * 4;
            float4 v = __ldg((const float4*)(Wmlp + (size_t)(E + k0 + br) * C + bc));
            __half2 h01 = __floats2half2_rn(v.x, v.y);
            __half2 h23 = __floats2half2_rn(v.z, v.w);
            uint2 pk; pk.x = *(unsigned*)&h01; pk.y = *(unsigned*)&h23;
            *(uint2*)(Bs + br * 136 + bc) = pk;
        }
        __syncthreads();
        mma_tile<136, 136>(As + k0, Bs, wm, wn, acc);
        __syncthreads();
    }

    // epilogue: acc -> Cs (union) -> fp16 Zh
    #pragma unroll
    for (int fi = 0; fi < 2; fi++)
        for (int fj = 0; fj < 2; fj++)
            wmma::store_matrix_sync(
                Cs + (wm * 32 + fi * 16) * 128 + wn * 32 + fj * 16,
                acc[fi][fj], 128, wmma::mem_row_major);
    __syncthreads();
    #pragma unroll
    for (int it = 0; it < 8; it++) {
        int idx = tid + 256 * it, row = idx >> 5, c4 = (idx & 31) * 4;
        float4 v = *(const float4*)(Cs + row * 128 + c4);
        __half2 h01 = __floats2half2_rn(v.x, v.y);
        __half2 h23 = __floats2half2_rn(v.z, v.w);
        uint2 pk; pk.x = *(unsigned*)&h01; pk.y = *(unsigned*)&h23;
        *(uint2*)(g_Zh + ((size_t)(u * J + j0 + row)) * C + c4) = pk;
    }
}

// ---------------- gemm_main: fused attention + pooling + MLP ----------------
// grid (I/64, U), 512 thr (16 warps), ~107 KB dynamic smem.
// Phase 0: st[64] (warp dots) + skb/mask -> smem.
// Phase 1: w = exp(tanh(st+skb))*mask -> wsm fp16 (all 16 warps); rowsum.
// Phase 2 (split): warps 0-7 MMA over J with cp.async double-buffered Bs;
//                  warps 8-15 stream normalized attn to gmem concurrently.
// Epilogue: relu(acc*inv + upart) -> out_ctx.
constexpr int LDW  = 528;                         // wsm half stride
constexpr int BOFF = 64 * LDW * 2;                // 67,584
constexpr int BS_STAGE = 64 * 136;                // halves per stage
constexpr int SOFF = BOFF + 2 * BS_STAGE * 2;     // 102,400
constexpr int SMEM_MAIN = SOFF + (64 + 64 + 512 + 512) * 4;  // 107,008

__global__ __launch_bounds__(512, 1) void gemm_main_kernel(
    const float* __restrict__ target, const float* __restrict__ w1,
    const void* __restrict__ mask,
    float* __restrict__ out_ctx, float* __restrict__ out_attn)
{
    extern __shared__ __align__(16) char dsm[];
    __half* wsm   = (__half*)dsm;
    __half* Bs    = (__half*)(dsm + BOFF);   // [2][64*136]
    float*  Cs    = (float*)(dsm + BOFF);    // union, used after MMA
    float* st_sm  = (float*)(dsm + SOFF);
    float* inv_sm = st_sm + 64;
    float* skb_sm = inv_sm + 64;
    float* m_sm   = skb_sm + 512;

    const int u = blockIdx.y, m0 = blockIdx.x * 64;
    const int tid = threadIdx.x, wid = tid >> 5, lane = tid & 31;
    const float L2E = 1.4426950408889634f;

    // phase 0: skb + mask (512 threads, 1 elem each) and st (warp per row)
    {
        int k = tid;
        skb_sm[k] = g_skb[u * J + k];
        int mode = g_mask_mode;
        float mv;
        if (mode == 1)      mv = ((const int*)mask)[u * J + k] ? 1.f : 0.f;
        else if (mode == 2) mv = ((const float*)mask)[u * J + k];
        else                mv = ((const unsigned char*)mask)[u * J + k] ? 1.f : 0.f;
        m_sm[k] = mv;
    }
    {
        float4 wv = __ldg((const float4*)w1 + lane);
        #pragma unroll
        for (int r = 0; r < 4; r++) {
            int row = wid + 16 * r;
            float4 v = *(const float4*)(target + ((size_t)(u * I + m0 + row)) * C + lane * 4);
            float d = v.x * wv.x + v.y * wv.y + v.z * wv.z + v.w * wv.w;
            #pragma unroll
            for (int off = 16; off; off >>= 1) d += __shfl_xor_sync(0xffffffffu, d, off);
            if (lane == 0) st_sm[row] = d;
        }
    }
    __syncthreads();

    // phase 1: 8 threads per row, interleaved half2 columns (bank-clean)
    {
        int row = tid >> 3, sub = tid & 7;
        float stv = st_sm[row];
        float sum = 0.f;
        #pragma unroll
        for (int k = 0; k < 32; k++) {
            int c = sub * 2 + 16 * k;
            float x0 = stv + skb_sm[c], x1 = stv + skb_sm[c + 1];
            float t0, t1, e0, e1;
            asm("tanh.approx.f32 %0,%1;" : "=f"(t0) : "f"(x0));
            asm("tanh.approx.f32 %0,%1;" : "=f"(t1) : "f"(x1));
            asm("ex2.approx.f32 %0,%1;"  : "=f"(e0) : "f"(t0 * L2E));
            asm("ex2.approx.f32 %0,%1;"  : "=f"(e1) : "f"(t1 * L2E));
            e0 *= m_sm[c]; e1 *= m_sm[c + 1];
            *(__half2*)(wsm + row * LDW + c) = __floats2half2_rn(e0, e1);
            sum += e0 + e1;
        }
        sum += __shfl_xor_sync(0xffffffffu, sum, 1);
        sum += __shfl_xor_sync(0xffffffffu, sum, 2);
        sum += __shfl_xor_sync(0xffffffffu, sum, 4);
        if (sub == 0) inv_sm[row] = __fdividef(1.f, sum);
    }
    __syncthreads();

    wmma::fragment<wmma::accumulator, 16, 16, 16, float> acc[2][2];

    if (tid < 256) {
        // ---- MMA warps: k-loop with double-buffered cp.async Bs ----
        const int wm = wid >> 2, wn = wid & 3;
        #pragma unroll
        for (int fi = 0; fi < 2; fi++)
            for (int fj = 0; fj < 2; fj++) wmma::fill_fragment(acc[fi][fj], 0.f);

        // prefetch tile 0
        {
            #pragma unroll
            for (int r = 0; r < 4; r++) {
                int idx = tid + 256 * r, br = idx >> 4, bc = (idx & 15) * 8;
                cp_async16(Bs + br * 136 + bc,
                           g_Zh + ((size_t)u * J + br) * C + bc);
            }
            cp_commit();
        }
        for (int kt = 0; kt < 8; kt++) {
            if (kt < 7) {
                __half* dst = Bs + ((kt + 1) & 1) * BS_STAGE;
                #pragma unroll
                for (int r = 0; r < 4; r++) {
                    int idx = tid + 256 * r, br = idx >> 4, bc = (idx & 15) * 8;
                    cp_async16(dst + br * 136 + bc,
                               g_Zh + ((size_t)u * J + (kt + 1) * 64 + br) * C + bc);
                }
                cp_commit();
                cp_wait<1>();
            } else {
                cp_wait<0>();
            }
            asm volatile("bar.sync 1, 256;" ::: "memory");
            mma_tile<LDW, 136>(wsm + kt * 64, Bs + (kt & 1) * BS_STAGE, wm, wn, acc);
            asm volatile("bar.sync 1, 256;" ::: "memory");
        }
    } else {
        // ---- store warps: normalized attn -> gmem (overlaps MMA) ----
        int t = tid - 256;
        float* ab = out_attn + ((size_t)(u * I + m0)) * J;
        #pragma unroll
        for (int it = 0; it < 32; it++) {
            int idx = t + 256 * it;             // 8192 float4s
            int row = idx >> 7, c4 = (idx & 127) * 4;
            uint2 pk = *(uint2*)(wsm + row * LDW + c4);
            __half2 h01 = *(__half2*)&pk.x, h23 = *(__half2*)&pk.y;
            float iv = inv_sm[row];
            float2 f01 = __half22float2(h01), f23 = __half22float2(h23);
            *(float4*)(ab + row * J + c4) =
                make_float4(f01.x * iv, f01.y * iv, f23.x * iv, f23.y * iv);
        }
    }
    __syncthreads();

    // epilogue: acc -> Cs (union over Bs), then relu(acc*inv + upart)
    if (tid < 256) {
        const int wm = wid >> 2, wn = wid & 3;
        #pragma unroll
        for (int fi = 0; fi < 2; fi++)
            for (int fj = 0; fj < 2; fj++)
                wmma::store_matrix_sync(
                    Cs + (wm * 32 + fi * 16) * 128 + wn * 32 + fj * 16,
                    acc[fi][fj], 128, wmma::mem_row_major);
    }
    __syncthreads();

    {
        const float4* up4 = (const float4*)(g_upart + u * C);
        float* ob = out_ctx + ((size_t)(u * I + m0)) * C;
        #pragma unroll
        for (int it = 0; it < 4; it++) {
            int idx = tid + 512 * it, row = idx >> 5, c4 = idx & 31;
            float4 v = ((const float4*)Cs)[idx];
            float iv = inv_sm[row];
            float4 up = __ldg(up4 + c4);
            v.x = fmaxf(fmaf(v.x, iv, up.x), 0.f);
            v.y = fmaxf(fmaf(v.y, iv, up.y), 0.f);
            v.z = fmaxf(fmaf(v.z, iv, up.z), 0.f);
            v.w = fmaxf(fmaf(v.w, iv, up.w), 0.f);
            ((float4*)ob)[idx] = v;
        }
    }
}

// ---------------- launcher ---------------------------------------------------
extern "C" void kernel_launch(void* const* d_in, const int* in_sizes, int n_in,
                              void* d_out, int out_size)
{
    const float* target = (const float*)d_in[0];  // (U,I,C)
    const float* inter  = (const float*)d_in[1];  // (U,J,C)
    const float* user   = (const float*)d_in[2];  // (U,E)
    const void*  mask   = d_in[3];                // (U,J) dtype sniffed
    const float* wdense = (const float*)d_in[4];  // (2C,)
    const float* bdense = (const float*)d_in[5];  // (1,)
    const float* Wmlp   = (const float*)d_in[6];  // (E+C, C)
    const float* bmlp   = (const float*)d_in[7];  // (C,)

    float* out_ctx  = (float*)d_out;                       // (U,I,C)
    float* out_attn = (float*)d_out + (size_t)U * I * C;   // (U,I,J)

    cudaFuncSetAttribute(gemm_main_kernel,
                         cudaFuncAttributeMaxDynamicSharedMemorySize, SMEM_MAIN);

    detect_mask_kernel<<<1, 1024>>>((const unsigned*)mask);
    fusedz_kernel<<<dim3(9, U), 256>>>(inter, wdense + C, bdense,
                                       user, Wmlp, bmlp);
    gemm_main_kernel<<<dim3(I / 64, U), 512, SMEM_MAIN>>>(target, wdense, mask,
                                                          out_ctx, out_attn);
}

// round 7
// speedup vs baseline: 1.6396x; 1.2497x over previous
#include <cuda_runtime.h>
#include <cuda_fp16.h>
#include <mma.h>
#include <cstdint>

using namespace nvcuda;

// Problem dims (fixed by setup_inputs)
constexpr int U = 128, I = 256, J = 512, C = 128, E = 128;

// ---------------- scratch (device globals) ----------------------------------
__device__ float  g_skb[U * J];            // inter . w2 + b
__device__ float  g_upart[U * C];          // user @ W1 + b_mlp
__device__ int    g_pa[32], g_pb[32];      // mask-sniff partial flags
__device__ __half g_Zh[U * J * C];         // Z = interacted @ W2, fp16

// ---------------- cp.async helpers ------------------------------------------
__device__ __forceinline__ void cp_async16(void* smem, const void* gmem)
{
    unsigned s = (unsigned)__cvta_generic_to_shared(smem);
    asm volatile("cp.async.cg.shared.global [%0], [%1], 16;" :: "r"(s), "l"(gmem));
}
__device__ __forceinline__ void cp_commit()
{
    asm volatile("cp.async.commit_group;" ::: "memory");
}
template<int N>
__device__ __forceinline__ void cp_wait()
{
    asm volatile("cp.async.wait_group %0;" :: "n"(N) : "memory");
}

// ---------------- MMA micro-tiles -------------------------------------------
template<int LDA, int LDB>
__device__ __forceinline__ void mma_tile64(
    const __half* A, const __half* B, int wm, int wn,
    wmma::fragment<wmma::accumulator, 16, 16, 16, float> (&acc)[2][2])
{
    #pragma unroll
    for (int kk = 0; kk < 64; kk += 16) {
        wmma::fragment<wmma::matrix_a, 16, 16, 16, __half, wmma::row_major> a[2];
        wmma::fragment<wmma::matrix_b, 16, 16, 16, __half, wmma::row_major> b[2];
        wmma::load_matrix_sync(a[0], A + (wm * 32) * LDA + kk, LDA);
        wmma::load_matrix_sync(a[1], A + (wm * 32 + 16) * LDA + kk, LDA);
        wmma::load_matrix_sync(b[0], B + kk * LDB + wn * 32, LDB);
        wmma::load_matrix_sync(b[1], B + kk * LDB + wn * 32 + 16, LDB);
        #pragma unroll
        for (int fi = 0; fi < 2; fi++)
            #pragma unroll
            for (int fj = 0; fj < 2; fj++)
                wmma::mma_sync(acc[fi][fj], a[fi], b[fj], acc[fi][fj]);
    }
}

template<int LDA, int LDB>
__device__ __forceinline__ void mma_tile128(
    const __half* A, const __half* B, int wm, int wn,
    wmma::fragment<wmma::accumulator, 16, 16, 16, float> (&acc)[4][2])
{
    #pragma unroll
    for (int kk = 0; kk < 64; kk += 16) {
        wmma::fragment<wmma::matrix_a, 16, 16, 16, __half, wmma::row_major> a[4];
        wmma::fragment<wmma::matrix_b, 16, 16, 16, __half, wmma::row_major> b[2];
        #pragma unroll
        for (int fi = 0; fi < 4; fi++)
            wmma::load_matrix_sync(a[fi], A + (wm * 64 + fi * 16) * LDA + kk, LDA);
        #pragma unroll
        for (int fj = 0; fj < 2; fj++)
            wmma::load_matrix_sync(b[fj], B + kk * LDB + wn * 32 + fj * 16, LDB);
        #pragma unroll
        for (int fi = 0; fi < 4; fi++)
            #pragma unroll
            for (int fj = 0; fj < 2; fj++)
                wmma::mma_sync(acc[fi][fj], a[fi], b[fj], acc[fi][fj]);
    }
}

// ---------------- fusedZ: inter -> skb + Zh fp16; upart + mask sniff ride --
// grid (10, U), 256 thr.
//   x<8 : 64 j-rows of user u (GEMM Z)
//   x==8: upart for u
//   x==9 && u<32: mask sniff partial (block u covers words [u*512, u*512+512))
__global__ __launch_bounds__(256) void fusedz_kernel(
    const float* __restrict__ inter, const float* __restrict__ w2,
    const float* __restrict__ bd, const float* __restrict__ user,
    const float* __restrict__ Wmlp, const float* __restrict__ bmlp,
    const unsigned* __restrict__ mask)
{
    __shared__ __align__(16) char sm[64 * 136 * 2 * 2];  // 34,816 B
    const int u = blockIdx.y;
    const int tid = threadIdx.x, wid = tid >> 5, lane = tid & 31;

    if (blockIdx.x == 9) {
        // ---- mask sniff partial ----
        if (u >= 32) return;
        int a = 0, b = 0;
        #pragma unroll
        for (int r = 0; r < 2; r++) {
            unsigned w = mask[u * 512 + tid + 256 * r];
            a |= (w != 0u && w != 1u);
            b |= (w != 0u && w != 0x3F800000u);
        }
        int* s_f = (int*)sm;
        if (tid == 0) { s_f[0] = 0; s_f[1] = 0; }
        __syncthreads();
        a = __reduce_or_sync(0xffffffffu, a);
        b = __reduce_or_sync(0xffffffffu, b);
        if (lane == 0) { atomicOr(&s_f[0], a); atomicOr(&s_f[1], b); }
        __syncthreads();
        if (tid == 0) { g_pa[u] = s_f[0]; g_pb[u] = s_f[1]; }
        return;
    }

    if (blockIdx.x == 8) {
        // ---- upart: g_upart[u] = user[u] @ Wmlp[:E] + bmlp ----
        float* usm  = (float*)sm;          // 128 floats
        float* psum = usm + 128;           // 256 floats
        if (tid < 128) usm[tid] = user[u * E + tid];
        __syncthreads();
        int c = tid & 127, h = tid >> 7;
        float acc0 = 0.f, acc1 = 0.f;
        int e0 = h * 64;
        #pragma unroll 16
        for (int e = 0; e < 64; e += 2) {
            acc0 += usm[e0 + e]     * __ldg(Wmlp + (e0 + e) * C + c);
            acc1 += usm[e0 + e + 1] * __ldg(Wmlp + (e0 + e + 1) * C + c);
        }
        psum[tid] = acc0 + acc1;
        __syncthreads();
        if (tid < 128)
            g_upart[u * C + tid] = psum[tid] + psum[tid + 128] + __ldg(bmlp + tid);
        return;
    }

    // ---- fusedz main path ----
    __half* As = (__half*)sm;                    // 64 x 128 (lda 136)
    __half* Bs = (__half*)(sm + 64 * 136 * 2);
    float*  Cs = (float*)sm;                     // epilogue staging (32 KB)
    const int j0 = blockIdx.x * 64;
    const int wm = wid >> 2, wn = wid & 3;

    const float4 wv = __ldg((const float4*)w2 + lane);
    const float bias = __ldg(bd);

    // load + convert + skb dot (warp per row, 8 rows per warp)
    #pragma unroll
    for (int r = 0; r < 8; r++) {
        int row = wid + 8 * r;
        float4 v = *(const float4*)(inter + ((size_t)(u * J + j0 + row)) * C + lane * 4);
        __half2 h01 = __floats2half2_rn(v.x, v.y);
        __half2 h23 = __floats2half2_rn(v.z, v.w);
        uint2 pk;
        pk.x = *(unsigned*)&h01; pk.y = *(unsigned*)&h23;
        *(uint2*)(As + row * 136 + lane * 4) = pk;
        float d = v.x * wv.x + v.y * wv.y + v.z * wv.z + v.w * wv.w;
        #pragma unroll
        for (int off = 16; off; off >>= 1) d += __shfl_xor_sync(0xffffffffu, d, off);
        if (lane == 0) g_skb[u * J + j0 + row] = d + bias;
    }
    __syncthreads();

    wmma::fragment<wmma::accumulator, 16, 16, 16, float> acc[2][2];
    #pragma unroll
    for (int fi = 0; fi < 2; fi++)
        for (int fj = 0; fj < 2; fj++) wmma::fill_fragment(acc[fi][fj], 0.f);

    for (int k0 = 0; k0 < C; k0 += 64) {
        // Bs <- W_mlp[E+k0 .. E+k0+63, :] converted fp32->fp16 (L2-hot)
        #pragma unroll
        for (int r = 0; r < 8; r++) {
            int idx = tid + 256 * r;
            int br = idx >> 5, bc = (idx & 31) * 4;
            float4 v = __ldg((const float4*)(Wmlp + (size_t)(E + k0 + br) * C + bc));
            __half2 h01 = __floats2half2_rn(v.x, v.y);
            __half2 h23 = __floats2half2_rn(v.z, v.w);
            uint2 pk; pk.x = *(unsigned*)&h01; pk.y = *(unsigned*)&h23;
            *(uint2*)(Bs + br * 136 + bc) = pk;
        }
        __syncthreads();
        mma_tile64<136, 136>(As + k0, Bs, wm, wn, acc);
        __syncthreads();
    }

    // epilogue: acc -> Cs (union) -> fp16 Zh
    #pragma unroll
    for (int fi = 0; fi < 2; fi++)
        for (int fj = 0; fj < 2; fj++)
            wmma::store_matrix_sync(
                Cs + (wm * 32 + fi * 16) * 128 + wn * 32 + fj * 16,
                acc[fi][fj], 128, wmma::mem_row_major);
    __syncthreads();
    #pragma unroll
    for (int it = 0; it < 8; it++) {
        int idx = tid + 256 * it, row = idx >> 5, c4 = (idx & 31) * 4;
        float4 v = *(const float4*)(Cs + row * 128 + c4);
        __half2 h01 = __floats2half2_rn(v.x, v.y);
        __half2 h23 = __floats2half2_rn(v.z, v.w);
        uint2 pk; pk.x = *(unsigned*)&h01; pk.y = *(unsigned*)&h23;
        *(uint2*)(g_Zh + ((size_t)(u * J + j0 + row)) * C + c4) = pk;
    }
}

// ---------------- gemm_main: fused attention + pooling + MLP ----------------
// grid (I/128, U), 512 thr (16 warps), 173 KB dynamic smem, BM=128.
// Phase 0: st[128] (warp dots) + skb/mask -> smem; mode from g_pa/g_pb.
// Phase 1: w = exp(tanh(st+skb))*mask -> wsm fp16 (128x512); rowsum -> inv.
// Phase 2 (split): warps 0-7 MMA over J with cp.async double-buffered Bs;
//                  warps 8-15 stream normalized attn (256 KB) concurrently.
// Epilogue: relu(acc*inv + upart) -> out_ctx (Cs unioned over wsm).
constexpr int BM   = 128;
constexpr int LDW  = 520;                         // wsm half stride (bank-free)
constexpr int BOFF = BM * LDW * 2;                // 133,120
constexpr int BS_STAGE = 64 * 136;                // halves per stage
constexpr int SOFF = BOFF + 2 * BS_STAGE * 2;     // 167,936
constexpr int SMEM_MAIN = SOFF + (128 + 128 + 512 + 512) * 4;  // 173,056

__global__ __launch_bounds__(512, 1) void gemm_main_kernel(
    const float* __restrict__ target, const float* __restrict__ w1,
    const void* __restrict__ mask,
    float* __restrict__ out_ctx, float* __restrict__ out_attn)
{
    extern __shared__ __align__(16) char dsm[];
    __half* wsm   = (__half*)dsm;            // 128 x 512 (ld 520)
    __half* Bs    = (__half*)(dsm + BOFF);   // [2][64*136]
    float*  Cs    = (float*)dsm;             // union over wsm, epilogue only
    float* st_sm  = (float*)(dsm + SOFF);
    float* inv_sm = st_sm + 128;
    float* skb_sm = inv_sm + 128;
    float* m_sm   = skb_sm + 512;

    const int u = blockIdx.y, m0 = blockIdx.x * BM;
    const int tid = threadIdx.x, wid = tid >> 5, lane = tid & 31;
    const float L2E = 1.4426950408889634f;

    // mask mode from partial flags (2 loads + warp-OR per thread)
    int fa = g_pa[lane], fb = g_pb[lane];
    fa = __reduce_or_sync(0xffffffffu, fa);
    fb = __reduce_or_sync(0xffffffffu, fb);
    const int mode = !fa ? 1 : (!fb ? 2 : 0);

    // phase 0: skb + mask (512 threads, 1 elem each) and st (warp per row)
    {
        int k = tid;
        skb_sm[k] = g_skb[u * J + k];
        float mv;
        if (mode == 1)      mv = ((const int*)mask)[u * J + k] ? 1.f : 0.f;
        else if (mode == 2) mv = ((const float*)mask)[u * J + k];
        else                mv = ((const unsigned char*)mask)[u * J + k] ? 1.f : 0.f;
        m_sm[k] = mv;
    }
    {
        float4 wv = __ldg((const float4*)w1 + lane);
        #pragma unroll
        for (int r = 0; r < 8; r++) {
            int row = wid + 16 * r;
            float4 v = *(const float4*)(target + ((size_t)(u * I + m0 + row)) * C + lane * 4);
            float d = v.x * wv.x + v.y * wv.y + v.z * wv.z + v.w * wv.w;
            #pragma unroll
            for (int off = 16; off; off >>= 1) d += __shfl_xor_sync(0xffffffffu, d, off);
            if (lane == 0) st_sm[row] = d;
        }
    }
    __syncthreads();

    // phase 1: 4 threads per row, interleaved half2 cols (bank-conflict-free)
    {
        int row = tid >> 2, sub = tid & 3;
        float stv = st_sm[row];
        float sum = 0.f;
        #pragma unroll
        for (int k = 0; k < 64; k++) {
            int c = sub * 2 + 8 * k;
            float x0 = stv + skb_sm[c], x1 = stv + skb_sm[c + 1];
            float t0, t1, e0, e1;
            asm("tanh.approx.f32 %0,%1;" : "=f"(t0) : "f"(x0));
            asm("tanh.approx.f32 %0,%1;" : "=f"(t1) : "f"(x1));
            asm("ex2.approx.f32 %0,%1;"  : "=f"(e0) : "f"(t0 * L2E));
            asm("ex2.approx.f32 %0,%1;"  : "=f"(e1) : "f"(t1 * L2E));
            e0 *= m_sm[c]; e1 *= m_sm[c + 1];
            *(__half2*)(wsm + row * LDW + c) = __floats2half2_rn(e0, e1);
            sum += e0 + e1;
        }
        sum += __shfl_xor_sync(0xffffffffu, sum, 1);
        sum += __shfl_xor_sync(0xffffffffu, sum, 2);
        if (sub == 0) inv_sm[row] = __fdividef(1.f, sum);
    }
    __syncthreads();

    wmma::fragment<wmma::accumulator, 16, 16, 16, float> acc[4][2];

    if (tid < 256) {
        // ---- MMA warps: k-loop, double-buffered cp.async Bs ----
        const int wm = wid >> 2, wn = wid & 3;
        #pragma unroll
        for (int fi = 0; fi < 4; fi++)
            for (int fj = 0; fj < 2; fj++) wmma::fill_fragment(acc[fi][fj], 0.f);

        #pragma unroll
        for (int r = 0; r < 4; r++) {
            int idx = tid + 256 * r, br = idx >> 4, bc = (idx & 15) * 8;
            cp_async16(Bs + br * 136 + bc, g_Zh + ((size_t)u * J + br) * C + bc);
        }
        cp_commit();

        for (int kt = 0; kt < 8; kt++) {
            if (kt < 7) {
                __half* dst = Bs + ((kt + 1) & 1) * BS_STAGE;
                #pragma unroll
                for (int r = 0; r < 4; r++) {
                    int idx = tid + 256 * r, br = idx >> 4, bc = (idx & 15) * 8;
                    cp_async16(dst + br * 136 + bc,
                               g_Zh + ((size_t)u * J + (kt + 1) * 64 + br) * C + bc);
                }
                cp_commit();
                cp_wait<1>();
            } else {
                cp_wait<0>();
            }
            asm volatile("bar.sync 1, 256;" ::: "memory");
            mma_tile128<LDW, 136>(wsm + kt * 64, Bs + (kt & 1) * BS_STAGE, wm, wn, acc);
            asm volatile("bar.sync 1, 256;" ::: "memory");
        }
    } else {
        // ---- store warps: normalized attn -> gmem (overlaps MMA) ----
        int t = tid - 256;
        float* ab = out_attn + ((size_t)(u * I + m0)) * J;
        #pragma unroll
        for (int it = 0; it < 64; it++) {
            int idx = t + 256 * it;             // 16384 float4s
            int row = idx >> 7, c4 = (idx & 127) * 4;
            uint2 pk = *(uint2*)(wsm + row * LDW + c4);
            __half2 h01 = *(__half2*)&pk.x, h23 = *(__half2*)&pk.y;
            float iv = inv_sm[row];
            float2 f01 = __half22float2(h01), f23 = __half22float2(h23);
            *(float4*)(ab + row * J + c4) =
                make_float4(f01.x * iv, f01.y * iv, f23.x * iv, f23.y * iv);
        }
    }
    __syncthreads();   // store warps done reading wsm; Cs may now alias it

    if (tid < 256) {
        const int wm = wid >> 2, wn = wid & 3;
        #pragma unroll
        for (int fi = 0; fi < 4; fi++)
            for (int fj = 0; fj < 2; fj++)
                wmma::store_matrix_sync(
                    Cs + (wm * 64 + fi * 16) * 128 + wn * 32 + fj * 16,
                    acc[fi][fj], 128, wmma::mem_row_major);
    }
    __syncthreads();

    {
        const float4* up4 = (const float4*)(g_upart + u * C);
        float* ob = out_ctx + ((size_t)(u * I + m0)) * C;
        #pragma unroll
        for (int it = 0; it < 8; it++) {
            int idx = tid + 512 * it, row = idx >> 5, c4 = idx & 31;
            float4 v = ((const float4*)Cs)[idx];
            float iv = inv_sm[row];
            float4 up = __ldg(up4 + c4);
            v.x = fmaxf(fmaf(v.x, iv, up.x), 0.f);
            v.y = fmaxf(fmaf(v.y, iv, up.y), 0.f);
            v.z = fmaxf(fmaf(v.z, iv, up.z), 0.f);
            v.w = fmaxf(fmaf(v.w, iv, up.w), 0.f);
            ((float4*)ob)[idx] = v;
        }
    }
}

// ---------------- launcher ---------------------------------------------------
extern "C" void kernel_launch(void* const* d_in, const int* in_sizes, int n_in,
                              void* d_out, int out_size)
{
    const float* target = (const float*)d_in[0];  // (U,I,C)
    const float* inter  = (const float*)d_in[1];  // (U,J,C)
    const float* user   = (const float*)d_in[2];  // (U,E)
    const void*  mask   = d_in[3];                // (U,J) dtype sniffed
    const float* wdense = (const float*)d_in[4];  // (2C,)
    const float* bdense = (const float*)d_in[5];  // (1,)
    const float* Wmlp   = (const float*)d_in[6];  // (E+C, C)
    const float* bmlp   = (const float*)d_in[7];  // (C,)

    float* out_ctx  = (float*)d_out;                       // (U,I,C)
    float* out_attn = (float*)d_out + (size_t)U * I * C;   // (U,I,J)

    cudaFuncSetAttribute(gemm_main_kernel,
                         cudaFuncAttributeMaxDynamicSharedMemorySize, SMEM_MAIN);

    fusedz_kernel<<<dim3(10, U), 256>>>(inter, wdense + C, bdense,
                                        user, Wmlp, bmlp,
                                        (const unsigned*)mask);
    gemm_main_kernel<<<dim3(I / BM, U), 512, SMEM_MAIN>>>(target, wdense, mask,
                                                          out_ctx, out_attn);
}